// round 3
// baseline (speedup 1.0000x reference)
#include <cuda_runtime.h>
#include <math.h>

#define B_ 16384
#define D_ 4096
#define H_ 2048
#define E_ 64
#define K_ 2
#define TEMP_INV 1.25f   // 1/0.8

// Scratch: hidden activations h = relu(x @ W1^T + b1), [B_, H_] fp32 (134 MB).
__device__ float g_h[(size_t)B_ * H_];
// Per-block entropy partial sums (router kernel grid = B_/64 = 256 blocks).
__device__ float g_ent[B_ / 64];

// ---------------------------------------------------------------------------
// Kernel 1: SGEMM 128x128x8, 256 threads, 8x8 per-thread tile, double-buffered
// C[b,hcol] = relu( sum_k x[b,k] * W1[hcol,k] + b1[hcol] )
// Both operands are K-contiguous (row-major [*, D]).
// ---------------------------------------------------------------------------
__global__ __launch_bounds__(256) void gemm1_relu_kernel(
    const float* __restrict__ x, const float* __restrict__ W1,
    const float* __restrict__ b1)
{
    __shared__ float As[2][8][128];
    __shared__ float Ws[2][8][128];

    const int bm = blockIdx.y * 128;   // batch rows
    const int bn = blockIdx.x * 128;   // hidden cols
    const int tid = threadIdx.x;

    // Global-load mapping: 128 rows x 8 k per tile = 1024 floats per operand.
    // 256 threads x float4: 2 threads per row.
    const int lr = tid >> 1;           // 0..127
    const int lk = (tid & 1) << 2;     // 0 or 4

    const float* xg = x  + (size_t)(bm + lr) * D_ + lk;
    const float* wg = W1 + (size_t)(bn + lr) * D_ + lk;

    const int tx = tid & 15;           // 16 thread cols (hidden dim)
    const int ty = tid >> 4;           // 16 thread rows (batch dim)

    float acc[8][8];
#pragma unroll
    for (int i = 0; i < 8; i++)
#pragma unroll
        for (int j = 0; j < 8; j++) acc[i][j] = 0.0f;

    // Prologue: load tile 0
    float4 a4 = *(const float4*)xg;
    float4 w4 = *(const float4*)wg;
    int s = 0;
    As[0][lk + 0][lr] = a4.x; As[0][lk + 1][lr] = a4.y;
    As[0][lk + 2][lr] = a4.z; As[0][lk + 3][lr] = a4.w;
    Ws[0][lk + 0][lr] = w4.x; Ws[0][lk + 1][lr] = w4.y;
    Ws[0][lk + 2][lr] = w4.z; Ws[0][lk + 3][lr] = w4.w;
    __syncthreads();

    const int NIT = D_ / 8;  // 512
    for (int it = 0; it < NIT; ++it) {
        if (it + 1 < NIT) {
            a4 = *(const float4*)(xg + (it + 1) * 8);
            w4 = *(const float4*)(wg + (it + 1) * 8);
        }
#pragma unroll
        for (int kk = 0; kk < 8; kk++) {
            float4 av0 = *(const float4*)&As[s][kk][ty * 8];
            float4 av1 = *(const float4*)&As[s][kk][ty * 8 + 4];
            float4 wv0 = *(const float4*)&Ws[s][kk][tx * 8];
            float4 wv1 = *(const float4*)&Ws[s][kk][tx * 8 + 4];
            float a[8] = {av0.x, av0.y, av0.z, av0.w, av1.x, av1.y, av1.z, av1.w};
            float w[8] = {wv0.x, wv0.y, wv0.z, wv0.w, wv1.x, wv1.y, wv1.z, wv1.w};
#pragma unroll
            for (int i = 0; i < 8; i++)
#pragma unroll
                for (int j = 0; j < 8; j++)
                    acc[i][j] = fmaf(a[i], w[j], acc[i][j]);
        }
        if (it + 1 < NIT) {
            s ^= 1;
            As[s][lk + 0][lr] = a4.x; As[s][lk + 1][lr] = a4.y;
            As[s][lk + 2][lr] = a4.z; As[s][lk + 3][lr] = a4.w;
            Ws[s][lk + 0][lr] = w4.x; Ws[s][lk + 1][lr] = w4.y;
            Ws[s][lk + 2][lr] = w4.z; Ws[s][lk + 3][lr] = w4.w;
            __syncthreads();
        }
    }

    // Epilogue: +bias, ReLU, store to g_h
    float bv[8];
#pragma unroll
    for (int j = 0; j < 8; j++) bv[j] = __ldg(&b1[bn + tx * 8 + j]);

#pragma unroll
    for (int i = 0; i < 8; i++) {
        const int row = bm + ty * 8 + i;
        float* op = g_h + (size_t)row * H_ + bn + tx * 8;
        float4 o0, o1;
        o0.x = fmaxf(acc[i][0] + bv[0], 0.0f);
        o0.y = fmaxf(acc[i][1] + bv[1], 0.0f);
        o0.z = fmaxf(acc[i][2] + bv[2], 0.0f);
        o0.w = fmaxf(acc[i][3] + bv[3], 0.0f);
        o1.x = fmaxf(acc[i][4] + bv[4], 0.0f);
        o1.y = fmaxf(acc[i][5] + bv[5], 0.0f);
        o1.z = fmaxf(acc[i][6] + bv[6], 0.0f);
        o1.w = fmaxf(acc[i][7] + bv[7], 0.0f);
        *(float4*)(op)     = o0;
        *(float4*)(op + 4) = o1;
    }
}

// ---------------------------------------------------------------------------
// Kernel 2: router GEMM 64rows x 64experts x K=2048 (BK=16) + softmax/top2/
// entropy epilogue. 256 threads, 4x4 per-thread tile.
// ---------------------------------------------------------------------------
__global__ __launch_bounds__(256) void router_kernel(
    const float* __restrict__ W2, const float* __restrict__ b2,
    float* __restrict__ out)
{
    __shared__ float Hs[2][16][64];
    __shared__ float Ws[2][16][64];
    __shared__ float logits[64][65];   // padded
    __shared__ float entbuf[64];

    const int bm = blockIdx.x * 64;    // batch rows
    const int tid = threadIdx.x;

    // Load mapping: 64 rows x 16 k = 1024 floats, 256 threads x float4
    const int lr = tid >> 2;           // 0..63
    const int lk = (tid & 3) << 2;     // 0,4,8,12

    const float* hg = g_h + (size_t)(bm + lr) * H_ + lk;
    const float* wg = W2  + (size_t)lr * H_ + lk;

    const int tx = tid & 15;           // expert tile col (16 x 4 experts)
    const int ty = tid >> 4;           // row tile (16 x 4 rows)

    float acc[4][4];
#pragma unroll
    for (int i = 0; i < 4; i++)
#pragma unroll
        for (int j = 0; j < 4; j++) acc[i][j] = 0.0f;

    float4 h4 = *(const float4*)hg;
    float4 w4 = *(const float4*)wg;
    int s = 0;
    Hs[0][lk + 0][lr] = h4.x; Hs[0][lk + 1][lr] = h4.y;
    Hs[0][lk + 2][lr] = h4.z; Hs[0][lk + 3][lr] = h4.w;
    Ws[0][lk + 0][lr] = w4.x; Ws[0][lk + 1][lr] = w4.y;
    Ws[0][lk + 2][lr] = w4.z; Ws[0][lk + 3][lr] = w4.w;
    __syncthreads();

    const int NIT = H_ / 16;  // 128
    for (int it = 0; it < NIT; ++it) {
        if (it + 1 < NIT) {
            h4 = *(const float4*)(hg + (it + 1) * 16);
            w4 = *(const float4*)(wg + (it + 1) * 16);
        }
#pragma unroll
        for (int kk = 0; kk < 16; kk++) {
            float4 hv = *(const float4*)&Hs[s][kk][ty * 4];
            float4 wv = *(const float4*)&Ws[s][kk][tx * 4];
            float a[4] = {hv.x, hv.y, hv.z, hv.w};
            float w[4] = {wv.x, wv.y, wv.z, wv.w};
#pragma unroll
            for (int i = 0; i < 4; i++)
#pragma unroll
                for (int j = 0; j < 4; j++)
                    acc[i][j] = fmaf(a[i], w[j], acc[i][j]);
        }
        if (it + 1 < NIT) {
            s ^= 1;
            Hs[s][lk + 0][lr] = h4.x; Hs[s][lk + 1][lr] = h4.y;
            Hs[s][lk + 2][lr] = h4.z; Hs[s][lk + 3][lr] = h4.w;
            Ws[s][lk + 0][lr] = w4.x; Ws[s][lk + 1][lr] = w4.y;
            Ws[s][lk + 2][lr] = w4.z; Ws[s][lk + 3][lr] = w4.w;
            __syncthreads();
        }
    }
    __syncthreads();

    // Write logits (+bias) to smem
#pragma unroll
    for (int i = 0; i < 4; i++)
#pragma unroll
        for (int j = 0; j < 4; j++) {
            const int e = tx * 4 + j;
            logits[ty * 4 + i][e] = acc[i][j] + __ldg(&b2[e]);
        }
    __syncthreads();

    // Per-row epilogue: softmax / top-2 / entropy. Threads 0..63 each own a row.
    float ent = 0.0f;
    if (tid < 64) {
        const int row = tid;
        float l[E_];
        float lmax = -INFINITY;
#pragma unroll
        for (int e = 0; e < E_; e++) {
            l[e] = logits[row][e];
            lmax = fmaxf(lmax, l[e]);
        }
        // top-2 (first-occurrence / lowest-index tie break, matching lax.top_k)
        int i1 = 0; float v1 = l[0];
#pragma unroll
        for (int e = 1; e < E_; e++)
            if (l[e] > v1) { v1 = l[e]; i1 = e; }
        int i2 = -1; float v2 = -INFINITY;
#pragma unroll
        for (int e = 0; e < E_; e++)
            if (e != i1 && l[e] > v2) { v2 = l[e]; i2 = e; }

        // renormalized top-2 weights of temperature softmax:
        // softmax normalization cancels, w1 = e1/(e1+e2)
        const float e1 = expf((v1 - lmax) * TEMP_INV);
        const float e2 = expf((v2 - lmax) * TEMP_INV);
        const float inv = 1.0f / (e1 + e2);
        const float w1 = e1 * inv;
        const float w2 = e2 * inv;

        // entropy of UN-scaled softmax
        float S = 0.0f;
#pragma unroll
        for (int e = 0; e < E_; e++) S += expf(l[e] - lmax);
        const float invS = 1.0f / S;
#pragma unroll
        for (int e = 0; e < E_; e++) {
            const float p = expf(l[e] - lmax) * invS;
            ent -= p * logf(p + 1e-10f);
        }

        const size_t grow = (size_t)bm + row;
        out[grow * 2 + 0] = w1;
        out[grow * 2 + 1] = w2;
        out[(size_t)B_ * K_ + grow * 2 + 0] = (float)i1;
        out[(size_t)B_ * K_ + grow * 2 + 1] = (float)i2;

        entbuf[tid] = ent;
    }
    __syncthreads();
    if (tid == 0) {
        float s2 = 0.0f;
#pragma unroll
        for (int r = 0; r < 64; r++) s2 += entbuf[r];
        g_ent[blockIdx.x] = s2;
    }
}

// ---------------------------------------------------------------------------
// Kernel 3: deterministic final entropy reduction -> uncertainty scalar
// (single warp, fixed summation order => deterministic)
// ---------------------------------------------------------------------------
__global__ void finalize_kernel(float* __restrict__ out)
{
    if (threadIdx.x == 0) {
        float s = 0.0f;
        for (int i = 0; i < B_ / 64; i++) s += g_ent[i];
        out[(size_t)2 * B_ * K_] = s / (float)B_ / logf((float)E_);
    }
}

// ---------------------------------------------------------------------------
extern "C" void kernel_launch(void* const* d_in, const int* in_sizes, int n_in,
                              void* d_out, int out_size)
{
    const float* x  = (const float*)d_in[0];
    const float* W1 = (const float*)d_in[1];
    const float* b1 = (const float*)d_in[2];
    const float* W2 = (const float*)d_in[3];
    const float* b2 = (const float*)d_in[4];
    float* out = (float*)d_out;

    dim3 g1(H_ / 128, B_ / 128);       // (16, 128)
    gemm1_relu_kernel<<<g1, 256>>>(x, W1, b1);
    router_kernel<<<B_ / 64, 256>>>(W2, b2, out);
    finalize_kernel<<<1, 32>>>(out);
}

// round 5
// speedup vs baseline: 2.3967x; 2.3967x over previous
#include <cuda_runtime.h>
#include <cuda_bf16.h>
#include <math.h>
#include <stdint.h>

#define B_ 16384
#define D_ 4096
#define H_ 2048
#define E_ 64
#define K_ 2
#define TEMP_INV 1.25f   // 1/0.8

// ---------------------------------------------------------------------------
// Scratch (device globals; no allocs allowed)
// ---------------------------------------------------------------------------
__device__ float g_h[(size_t)B_ * H_];                   // relu(x@W1^T+b1)
__device__ float g_ent[B_ / 64];
__device__ __nv_bfloat16 g_xs[(size_t)B_ * 2 * D_];      // [B][hi(D)|lo(D)]
__device__ __nv_bfloat16 g_ws[(size_t)H_ * 2 * D_];      // [H][hi(D)|lo(D)]

// ---------------------------------------------------------------------------
// Split kernels: 2-way bf16 decomposition x = hi + lo (lo = bf16(x - hi))
// ---------------------------------------------------------------------------
__device__ __forceinline__ void split2(float v, uint16_t& h, uint16_t& l) {
    __nv_bfloat16 hb = __float2bfloat16_rn(v);
    float r = v - __bfloat162float(hb);
    __nv_bfloat16 lb = __float2bfloat16_rn(r);
    h = __bfloat16_as_ushort(hb);
    l = __bfloat16_as_ushort(lb);
}

template <int ROWS, int COLS>
__device__ __forceinline__ void split2_body(const float* __restrict__ src,
                                            __nv_bfloat16* __restrict__ dst) {
    const size_t n4 = (size_t)ROWS * COLS / 4;
    for (size_t i = (size_t)blockIdx.x * blockDim.x + threadIdx.x; i < n4;
         i += (size_t)gridDim.x * blockDim.x) {
        const int r = (int)(i / (COLS / 4));
        const int c = (int)(i % (COLS / 4)) * 4;
        float4 v = *(const float4*)(src + (size_t)r * COLS + c);
        uint16_t h[4], l[4];
        split2(v.x, h[0], l[0]);
        split2(v.y, h[1], l[1]);
        split2(v.z, h[2], l[2]);
        split2(v.w, h[3], l[3]);
        __nv_bfloat16* row = dst + (size_t)r * (2 * COLS);
        uint2 uh = {(uint32_t)h[0] | ((uint32_t)h[1] << 16),
                    (uint32_t)h[2] | ((uint32_t)h[3] << 16)};
        uint2 ul = {(uint32_t)l[0] | ((uint32_t)l[1] << 16),
                    (uint32_t)l[2] | ((uint32_t)l[3] << 16)};
        *(uint2*)(row + c)        = uh;
        *(uint2*)(row + COLS + c) = ul;
    }
}

__global__ __launch_bounds__(256) void split_x_kernel(const float* __restrict__ x) {
    split2_body<B_, D_>(x, g_xs);
}
__global__ __launch_bounds__(256) void split_w_kernel(const float* __restrict__ W1) {
    split2_body<H_, D_>(W1, g_ws);
}

// ---------------------------------------------------------------------------
// GEMM1 via mma.sync bf16 (baseline PTX, works on .target sm_103):
//   h = relu( xh*wh + xh*wl + xl*wh + b1 )   (drops xl*wl ~ 2^-16)
// CTA tile 128x128, Kt=32, 8 warps (32x64 warp tiles), 4-stage cp.async.
// smem row stride 80B (64B data + 16B pad) => conflict-free ldmatrix.
// ---------------------------------------------------------------------------
#define TM 128
#define TN 128
#define KT 32
#define NSTAGE 4
#define ROWB 80                       // smem bytes per row (64 + 16 pad)
#define STAGE_B (2 * 128 * ROWB)      // A(128 rows) + B(128 rows) = 20480
#define GEMM_SMEM (NSTAGE * STAGE_B)  // 81920
#define NPASS 3
#define NT (NPASS * (D_ / KT))        // 384 flat k-tiles

__device__ __forceinline__ void cp16(uint32_t smem, const void* g) {
    asm volatile("cp.async.cg.shared.global [%0], [%1], 16;"
                 :: "r"(smem), "l"(g) : "memory");
}
#define CP_COMMIT() asm volatile("cp.async.commit_group;" ::: "memory")
#define CP_WAIT2()  asm volatile("cp.async.wait_group 2;" ::: "memory")
#define CP_WAIT0()  asm volatile("cp.async.wait_group 0;" ::: "memory")

__device__ __forceinline__ void ldmatrix4(uint32_t& r0, uint32_t& r1,
                                          uint32_t& r2, uint32_t& r3, uint32_t a) {
    asm volatile("ldmatrix.sync.aligned.m8n8.x4.shared.b16 {%0,%1,%2,%3}, [%4];"
                 : "=r"(r0), "=r"(r1), "=r"(r2), "=r"(r3) : "r"(a));
}

__device__ __forceinline__ void mma16816(float* c, uint32_t a0, uint32_t a1,
                                         uint32_t a2, uint32_t a3,
                                         uint32_t b0, uint32_t b1) {
    asm volatile(
        "mma.sync.aligned.m16n8k16.row.col.f32.bf16.bf16.f32 "
        "{%0,%1,%2,%3}, {%4,%5,%6,%7}, {%8,%9}, {%0,%1,%2,%3};"
        : "+f"(c[0]), "+f"(c[1]), "+f"(c[2]), "+f"(c[3])
        : "r"(a0), "r"(a1), "r"(a2), "r"(a3), "r"(b0), "r"(b1));
}

__device__ __forceinline__ void load_tile(uint32_t sbase, int kt, int st,
                                          int bm, int bn, int tid) {
    const int pass = kt >> 7;          // 0,1,2
    const int kk   = kt & 127;         // k-tile within pass
    const int aoff = (pass == 2) ? D_ : 0;   // xl on pass 2
    const int boff = (pass == 1) ? D_ : 0;   // wl on pass 1
    const uint32_t stA = sbase + st * STAGE_B;
    const uint32_t stB = stA + 128 * ROWB;
#pragma unroll
    for (int j = 0; j < 4; j++) {
        const int c = tid + (j << 8);         // 0..1023
        const int op  = c >> 9;               // 0=A, 1=B
        const int r   = (c >> 2) & 127;       // row 0..127
        const int seg = c & 3;                // 16B segment
        const int col = kk * KT + seg * 8;    // bf16 elem within D
        if (op == 0) {
            const __nv_bfloat16* g = g_xs + (size_t)(bm + r) * (2 * D_) + aoff + col;
            cp16(stA + r * ROWB + seg * 16, g);
        } else {
            const __nv_bfloat16* g = g_ws + (size_t)(bn + r) * (2 * D_) + boff + col;
            cp16(stB + r * ROWB + seg * 16, g);
        }
    }
}

__device__ __forceinline__ uint32_t smem_u32(const void* p) {
    uint32_t a;
    asm("{ .reg .u64 t; cvta.to.shared.u64 t, %1; cvt.u32.u64 %0, t; }"
        : "=r"(a) : "l"(p));
    return a;
}

__global__ __launch_bounds__(256, 2) void gemm1_mma_kernel(const float* __restrict__ b1) {
    extern __shared__ char smem[];
    const uint32_t sbase = smem_u32(smem);
    const int tid  = threadIdx.x;
    const int wid  = tid >> 5;
    const int lane = tid & 31;
    const int bm = blockIdx.x * TM;
    const int bn = blockIdx.y * TN;
    const int wm = (wid & 3) * 32;     // warp M offset (4 warps in M)
    const int wn = (wid >> 2) * 64;    // warp N offset (2 warps in N)

    float acc[2][8][4];
#pragma unroll
    for (int i = 0; i < 2; i++)
#pragma unroll
        for (int j = 0; j < 8; j++)
#pragma unroll
            for (int k = 0; k < 4; k++) acc[i][j][k] = 0.0f;

    // Prologue: stages 0..2
    load_tile(sbase, 0, 0, bm, bn, tid); CP_COMMIT();
    load_tile(sbase, 1, 1, bm, bn, tid); CP_COMMIT();
    load_tile(sbase, 2, 2, bm, bn, tid); CP_COMMIT();

    // Fragment address pre-computation (byte offsets inside a stage)
    const int aRow = wm + (lane & 15);
    const int aColB = (lane >> 4) * 16;           // 0 or 16 bytes
    const int bRow = wn + (lane & 7) + ((lane >> 4) & 1) * 8;
    const int bColB = ((lane >> 3) & 1) * 16;     // 0 or 16 bytes

    for (int kt = 0; kt < NT; kt++) {
        CP_WAIT2();
        __syncthreads();
        const int ktl = kt + 3;
        if (ktl < NT) load_tile(sbase, ktl, ktl & 3, bm, bn, tid);
        CP_COMMIT();

        const uint32_t stA = sbase + (kt & 3) * STAGE_B;
        const uint32_t stB = stA + 128 * ROWB;
#pragma unroll
        for (int k16 = 0; k16 < 2; k16++) {
            const int kB = k16 * 32;   // 16 bf16 = 32 bytes
            // A fragments: 2 m16 tiles
            uint32_t a[2][4];
#pragma unroll
            for (int tm = 0; tm < 2; tm++) {
                const uint32_t addr = stA + (aRow + tm * 16) * ROWB + kB + aColB;
                ldmatrix4(a[tm][0], a[tm][1], a[tm][2], a[tm][3], addr);
            }
            // B fragments: 8 n8 tiles via 4 x ldmatrix.x4 (pairs of n-tiles)
            uint32_t b[8][2];
#pragma unroll
            for (int tp = 0; tp < 4; tp++) {
                const uint32_t addr = stB + (bRow + tp * 16) * ROWB + kB + bColB;
                uint32_t r0, r1, r2, r3;
                ldmatrix4(r0, r1, r2, r3, addr);
                b[tp * 2 + 0][0] = r0; b[tp * 2 + 0][1] = r1;
                b[tp * 2 + 1][0] = r2; b[tp * 2 + 1][1] = r3;
            }
#pragma unroll
            for (int tm = 0; tm < 2; tm++)
#pragma unroll
                for (int tn = 0; tn < 8; tn++)
                    mma16816(acc[tm][tn], a[tm][0], a[tm][1], a[tm][2], a[tm][3],
                             b[tn][0], b[tn][1]);
        }
    }
    CP_WAIT0();

    // Epilogue: bias + relu -> g_h
    const int gid = lane >> 2;        // 0..7
    const int tig = lane & 3;         // 0..3
#pragma unroll
    for (int tn = 0; tn < 8; tn++) {
        const int col = bn + wn + tn * 8 + tig * 2;
        const float bv0 = __ldg(&b1[col]);
        const float bv1 = __ldg(&b1[col + 1]);
#pragma unroll
        for (int tm = 0; tm < 2; tm++) {
            const int row0 = bm + wm + tm * 16 + gid;
            float2 o0, o1;
            o0.x = fmaxf(acc[tm][tn][0] + bv0, 0.0f);
            o0.y = fmaxf(acc[tm][tn][1] + bv1, 0.0f);
            o1.x = fmaxf(acc[tm][tn][2] + bv0, 0.0f);
            o1.y = fmaxf(acc[tm][tn][3] + bv1, 0.0f);
            *(float2*)(g_h + (size_t)row0 * H_ + col)       = o0;
            *(float2*)(g_h + (size_t)(row0 + 8) * H_ + col) = o1;
        }
    }
}

// ---------------------------------------------------------------------------
// Kernel 2: router GEMM 64rows x 64experts x K=2048 + softmax/top2/entropy
// (fp32 SIMT — exact; unchanged from the passing Round-3 kernel)
// ---------------------------------------------------------------------------
__global__ __launch_bounds__(256) void router_kernel(
    const float* __restrict__ W2, const float* __restrict__ b2,
    float* __restrict__ out)
{
    __shared__ float Hs[2][16][64];
    __shared__ float Ws[2][16][64];
    __shared__ float logits[64][65];
    __shared__ float entbuf[64];

    const int bm = blockIdx.x * 64;
    const int tid = threadIdx.x;

    const int lr = tid >> 2;
    const int lk = (tid & 3) << 2;

    const float* hg = g_h + (size_t)(bm + lr) * H_ + lk;
    const float* wg = W2  + (size_t)lr * H_ + lk;

    const int tx = tid & 15;
    const int ty = tid >> 4;

    float acc[4][4];
#pragma unroll
    for (int i = 0; i < 4; i++)
#pragma unroll
        for (int j = 0; j < 4; j++) acc[i][j] = 0.0f;

    float4 h4 = *(const float4*)hg;
    float4 w4 = *(const float4*)wg;
    int s = 0;
    Hs[0][lk + 0][lr] = h4.x; Hs[0][lk + 1][lr] = h4.y;
    Hs[0][lk + 2][lr] = h4.z; Hs[0][lk + 3][lr] = h4.w;
    Ws[0][lk + 0][lr] = w4.x; Ws[0][lk + 1][lr] = w4.y;
    Ws[0][lk + 2][lr] = w4.z; Ws[0][lk + 3][lr] = w4.w;
    __syncthreads();

    const int NIT = H_ / 16;
    for (int it = 0; it < NIT; ++it) {
        if (it + 1 < NIT) {
            h4 = *(const float4*)(hg + (it + 1) * 16);
            w4 = *(const float4*)(wg + (it + 1) * 16);
        }
#pragma unroll
        for (int kk = 0; kk < 16; kk++) {
            float4 hv = *(const float4*)&Hs[s][kk][ty * 4];
            float4 wv = *(const float4*)&Ws[s][kk][tx * 4];
            float a[4] = {hv.x, hv.y, hv.z, hv.w};
            float w[4] = {wv.x, wv.y, wv.z, wv.w};
#pragma unroll
            for (int i = 0; i < 4; i++)
#pragma unroll
                for (int j = 0; j < 4; j++)
                    acc[i][j] = fmaf(a[i], w[j], acc[i][j]);
        }
        if (it + 1 < NIT) {
            s ^= 1;
            Hs[s][lk + 0][lr] = h4.x; Hs[s][lk + 1][lr] = h4.y;
            Hs[s][lk + 2][lr] = h4.z; Hs[s][lk + 3][lr] = h4.w;
            Ws[s][lk + 0][lr] = w4.x; Ws[s][lk + 1][lr] = w4.y;
            Ws[s][lk + 2][lr] = w4.z; Ws[s][lk + 3][lr] = w4.w;
            __syncthreads();
        }
    }
    __syncthreads();

#pragma unroll
    for (int i = 0; i < 4; i++)
#pragma unroll
        for (int j = 0; j < 4; j++) {
            const int e = tx * 4 + j;
            logits[ty * 4 + i][e] = acc[i][j] + __ldg(&b2[e]);
        }
    __syncthreads();

    float ent = 0.0f;
    if (tid < 64) {
        const int row = tid;
        float l[E_];
        float lmax = -INFINITY;
#pragma unroll
        for (int e = 0; e < E_; e++) {
            l[e] = logits[row][e];
            lmax = fmaxf(lmax, l[e]);
        }
        int i1 = 0; float v1 = l[0];
#pragma unroll
        for (int e = 1; e < E_; e++)
            if (l[e] > v1) { v1 = l[e]; i1 = e; }
        int i2 = -1; float v2 = -INFINITY;
#pragma unroll
        for (int e = 0; e < E_; e++)
            if (e != i1 && l[e] > v2) { v2 = l[e]; i2 = e; }

        const float e1 = expf((v1 - lmax) * TEMP_INV);
        const float e2 = expf((v2 - lmax) * TEMP_INV);
        const float inv = 1.0f / (e1 + e2);
        const float w1 = e1 * inv;
        const float w2 = e2 * inv;

        float S = 0.0f;
#pragma unroll
        for (int e = 0; e < E_; e++) S += expf(l[e] - lmax);
        const float invS = 1.0f / S;
#pragma unroll
        for (int e = 0; e < E_; e++) {
            const float p = expf(l[e] - lmax) * invS;
            ent -= p * logf(p + 1e-10f);
        }

        const size_t grow = (size_t)bm + row;
        out[grow * 2 + 0] = w1;
        out[grow * 2 + 1] = w2;
        out[(size_t)B_ * K_ + grow * 2 + 0] = (float)i1;
        out[(size_t)B_ * K_ + grow * 2 + 1] = (float)i2;

        entbuf[tid] = ent;
    }
    __syncthreads();
    if (tid == 0) {
        float s2 = 0.0f;
#pragma unroll
        for (int r = 0; r < 64; r++) s2 += entbuf[r];
        g_ent[blockIdx.x] = s2;
    }
}

__global__ void finalize_kernel(float* __restrict__ out)
{
    if (threadIdx.x == 0) {
        float s = 0.0f;
        for (int i = 0; i < B_ / 64; i++) s += g_ent[i];
        out[(size_t)2 * B_ * K_] = s / (float)B_ / logf((float)E_);
    }
}

// ---------------------------------------------------------------------------
extern "C" void kernel_launch(void* const* d_in, const int* in_sizes, int n_in,
                              void* d_out, int out_size)
{
    const float* x  = (const float*)d_in[0];
    const float* W1 = (const float*)d_in[1];
    const float* b1 = (const float*)d_in[2];
    const float* W2 = (const float*)d_in[3];
    const float* b2 = (const float*)d_in[4];
    float* out = (float*)d_out;

    static int smem_set = 0;
    if (!smem_set) {
        cudaFuncSetAttribute(gemm1_mma_kernel,
                             cudaFuncAttributeMaxDynamicSharedMemorySize, GEMM_SMEM);
        smem_set = 1;
    }

    split_x_kernel<<<2048, 256>>>(x);
    split_w_kernel<<<512, 256>>>(W1);

    dim3 g1(B_ / TM, H_ / TN);   // (128, 16)
    gemm1_mma_kernel<<<g1, 256, GEMM_SMEM>>>(b1);

    router_kernel<<<B_ / 64, 256>>>(W2, b2, out);
    finalize_kernel<<<1, 32>>>(out);
}

// round 7
// speedup vs baseline: 2.6550x; 1.1078x over previous
#include <cuda_runtime.h>
#include <cuda_bf16.h>
#include <math.h>
#include <stdint.h>

#define B_ 16384
#define D_ 4096
#define H_ 2048
#define E_ 64
#define K_ 2
#define TEMP_INV 1.25f   // 1/0.8

// ---------------------------------------------------------------------------
// Scratch (device globals; no allocs allowed)
// ---------------------------------------------------------------------------
__device__ float g_h[(size_t)B_ * H_];                   // relu(x@W1^T+b1)
__device__ float g_ent[B_ / 64];
__device__ __nv_bfloat16 g_xs[(size_t)B_ * 2 * D_];      // [B][hi(D)|lo(D)]
__device__ __nv_bfloat16 g_ws[(size_t)H_ * 2 * D_];      // [H][hi(D)|lo(D)]

// ---------------------------------------------------------------------------
// Split: 2-way bf16 decomposition x = hi + lo (lo = bf16(x - hi)), fused
// kernel handling both x and W1.
// ---------------------------------------------------------------------------
__device__ __forceinline__ void split2(float v, uint16_t& h, uint16_t& l) {
    __nv_bfloat16 hb = __float2bfloat16_rn(v);
    float r = v - __bfloat162float(hb);
    __nv_bfloat16 lb = __float2bfloat16_rn(r);
    h = __bfloat16_as_ushort(hb);
    l = __bfloat16_as_ushort(lb);
}

__device__ __forceinline__ void split2_body(const float* __restrict__ src,
                                            __nv_bfloat16* __restrict__ dst,
                                            int rows, int cols,
                                            int bid, int nblocks) {
    const size_t n4 = (size_t)rows * cols / 4;
    for (size_t i = (size_t)bid * blockDim.x + threadIdx.x; i < n4;
         i += (size_t)nblocks * blockDim.x) {
        const int r = (int)(i / (cols / 4));
        const int c = (int)(i % (cols / 4)) * 4;
        float4 v = *(const float4*)(src + (size_t)r * cols + c);
        uint16_t h[4], l[4];
        split2(v.x, h[0], l[0]);
        split2(v.y, h[1], l[1]);
        split2(v.z, h[2], l[2]);
        split2(v.w, h[3], l[3]);
        __nv_bfloat16* row = dst + (size_t)r * (2 * cols);
        uint2 uh = {(uint32_t)h[0] | ((uint32_t)h[1] << 16),
                    (uint32_t)h[2] | ((uint32_t)h[3] << 16)};
        uint2 ul = {(uint32_t)l[0] | ((uint32_t)l[1] << 16),
                    (uint32_t)l[2] | ((uint32_t)l[3] << 16)};
        *(uint2*)(row + c)        = uh;
        *(uint2*)(row + cols + c) = ul;
    }
}

#define SPLIT_XB 2048
#define SPLIT_NB 2304
__global__ __launch_bounds__(256) void split_both_kernel(
    const float* __restrict__ x, const float* __restrict__ W1) {
    if (blockIdx.x < SPLIT_XB)
        split2_body(x, g_xs, B_, D_, blockIdx.x, SPLIT_XB);
    else
        split2_body(W1, g_ws, H_, D_, blockIdx.x - SPLIT_XB, SPLIT_NB - SPLIT_XB);
}

// ---------------------------------------------------------------------------
// GEMM1 via mma.sync bf16: h = relu( xh*wh + xh*wl + xl*wh + b1 )
// CTA 128x128, KT=64, 3-stage cp.async pipeline, 8 warps (32x64 warp tiles).
// Row stride 144B (128B data + 16B pad) => conflict-free ldmatrix.
// ---------------------------------------------------------------------------
#define TM 128
#define TN 128
#define KT 64
#define NSTAGE 3
#define ROWB 144
#define STAGE_B (256 * ROWB)            // A(128 rows) + B(128 rows) = 36864
#define GEMM_SMEM (NSTAGE * STAGE_B)    // 110592
#define NPASS 3
#define NT (NPASS * (D_ / KT))          // 192 k-tiles

__device__ __forceinline__ void cp16(uint32_t smem, const void* g) {
    asm volatile("cp.async.cg.shared.global [%0], [%1], 16;"
                 :: "r"(smem), "l"(g) : "memory");
}
#define CP_COMMIT() asm volatile("cp.async.commit_group;" ::: "memory")
#define CP_WAIT1()  asm volatile("cp.async.wait_group 1;" ::: "memory")

__device__ __forceinline__ void ldmatrix4(uint32_t& r0, uint32_t& r1,
                                          uint32_t& r2, uint32_t& r3, uint32_t a) {
    asm volatile("ldmatrix.sync.aligned.m8n8.x4.shared.b16 {%0,%1,%2,%3}, [%4];"
                 : "=r"(r0), "=r"(r1), "=r"(r2), "=r"(r3) : "r"(a));
}

__device__ __forceinline__ void mma16816(float* c, uint32_t a0, uint32_t a1,
                                         uint32_t a2, uint32_t a3,
                                         uint32_t b0, uint32_t b1) {
    asm volatile(
        "mma.sync.aligned.m16n8k16.row.col.f32.bf16.bf16.f32 "
        "{%0,%1,%2,%3}, {%4,%5,%6,%7}, {%8,%9}, {%0,%1,%2,%3};"
        : "+f"(c[0]), "+f"(c[1]), "+f"(c[2]), "+f"(c[3])
        : "r"(a0), "r"(a1), "r"(a2), "r"(a3), "r"(b0), "r"(b1));
}

__device__ __forceinline__ void load_tile(uint32_t sbase, int kt, int st,
                                          int bm, int bn, int tid) {
    const int pass = kt >> 6;                // 64 ktiles per pass
    const int kk   = kt & 63;
    const int aoff = (pass == 2) ? D_ : 0;   // xl on pass 2
    const int boff = (pass == 1) ? D_ : 0;   // wl on pass 1
    const uint32_t stA = sbase + st * STAGE_B;
    const uint32_t stB = stA + 128 * ROWB;
#pragma unroll
    for (int j = 0; j < 8; j++) {
        const int c = tid + (j << 8);         // 0..2047
        const int r   = (c >> 3) & 127;       // row 0..127
        const int seg = c & 7;                 // 16B segment within 128B
        const int col = kk * KT + seg * 8;
        if (c < 1024) {
            const __nv_bfloat16* g = g_xs + (size_t)(bm + r) * (2 * D_) + aoff + col;
            cp16(stA + r * ROWB + seg * 16, g);
        } else {
            const __nv_bfloat16* g = g_ws + (size_t)(bn + r) * (2 * D_) + boff + col;
            cp16(stB + r * ROWB + seg * 16, g);
        }
    }
}

__device__ __forceinline__ uint32_t smem_u32(const void* p) {
    uint32_t a;
    asm("{ .reg .u64 t; cvta.to.shared.u64 t, %1; cvt.u32.u64 %0, t; }"
        : "=r"(a) : "l"(p));
    return a;
}

__global__ __launch_bounds__(256, 2) void gemm1_mma_kernel(const float* __restrict__ b1) {
    extern __shared__ char smem[];
    const uint32_t sbase = smem_u32(smem);
    const int tid  = threadIdx.x;
    const int wid  = tid >> 5;
    const int lane = tid & 31;
    const int bm = blockIdx.x * TM;
    const int bn = blockIdx.y * TN;
    const int wm = (wid & 3) * 32;     // 4 warps in M
    const int wn = (wid >> 2) * 64;    // 2 warps in N

    float acc[2][8][4];
#pragma unroll
    for (int i = 0; i < 2; i++)
#pragma unroll
        for (int j = 0; j < 8; j++)
#pragma unroll
            for (int k = 0; k < 4; k++) acc[i][j][k] = 0.0f;

    // Prologue: stages 0,1 in flight
    load_tile(sbase, 0, 0, bm, bn, tid); CP_COMMIT();
    load_tile(sbase, 1, 1, bm, bn, tid); CP_COMMIT();

    // Fragment smem offsets (relative to the stage's A base), hoisted
    const int aRow  = wm + (lane & 15);
    const int aColB = (lane >> 4) * 16;
    const int bRow  = wn + (lane & 7) + ((lane >> 4) & 1) * 8;
    const int bColB = ((lane >> 3) & 1) * 16;
    uint32_t aOff[2], bOff[4];
#pragma unroll
    for (int tm = 0; tm < 2; tm++) aOff[tm] = (aRow + tm * 16) * ROWB + aColB;
#pragma unroll
    for (int tp = 0; tp < 4; tp++) bOff[tp] = 128 * ROWB + (bRow + tp * 16) * ROWB + bColB;

    CP_WAIT1();            // stage 0 ready
    __syncthreads();

    int st = 0, ldst = 2;
    for (int kt = 0; kt < NT; kt++) {
        // Issue loads for stage kt+2 (overwrites stage kt-1; safe: bottom sync
        // of iter kt-1 guaranteed all warps finished reading it).
        if (kt + 2 < NT) load_tile(sbase, kt + 2, ldst, bm, bn, tid);
        CP_COMMIT();

        const uint32_t stA = sbase + st * STAGE_B;
#pragma unroll
        for (int k16 = 0; k16 < 4; k16++) {
            const int kB = k16 * 32;
            uint32_t a[2][4];
#pragma unroll
            for (int tm = 0; tm < 2; tm++)
                ldmatrix4(a[tm][0], a[tm][1], a[tm][2], a[tm][3], stA + aOff[tm] + kB);
            uint32_t b[8][2];
#pragma unroll
            for (int tp = 0; tp < 4; tp++) {
                uint32_t r0, r1, r2, r3;
                ldmatrix4(r0, r1, r2, r3, stA + bOff[tp] + kB);
                b[tp * 2 + 0][0] = r0; b[tp * 2 + 0][1] = r1;
                b[tp * 2 + 1][0] = r2; b[tp * 2 + 1][1] = r3;
            }
#pragma unroll
            for (int tm = 0; tm < 2; tm++)
#pragma unroll
                for (int tn = 0; tn < 8; tn++)
                    mma16816(acc[tm][tn], a[tm][0], a[tm][1], a[tm][2], a[tm][3],
                             b[tn][0], b[tn][1]);
        }
        st   = (st   == 2) ? 0 : st + 1;
        ldst = (ldst == 2) ? 0 : ldst + 1;
        CP_WAIT1();        // next stage arrived (hidden under the MMAs above)
        __syncthreads();
    }

    // Epilogue: bias + relu -> g_h
    const int gid = lane >> 2;
    const int tig = lane & 3;
#pragma unroll
    for (int tn = 0; tn < 8; tn++) {
        const int col = bn + wn + tn * 8 + tig * 2;
        const float bv0 = __ldg(&b1[col]);
        const float bv1 = __ldg(&b1[col + 1]);
#pragma unroll
        for (int tm = 0; tm < 2; tm++) {
            const int row0 = bm + wm + tm * 16 + gid;
            float2 o0, o1;
            o0.x = fmaxf(acc[tm][tn][0] + bv0, 0.0f);
            o0.y = fmaxf(acc[tm][tn][1] + bv1, 0.0f);
            o1.x = fmaxf(acc[tm][tn][2] + bv0, 0.0f);
            o1.y = fmaxf(acc[tm][tn][3] + bv1, 0.0f);
            *(float2*)(g_h + (size_t)row0 * H_ + col)       = o0;
            *(float2*)(g_h + (size_t)(row0 + 8) * H_ + col) = o1;
        }
    }
}

// ---------------------------------------------------------------------------
// Kernel 2: router GEMM 64rows x 64experts x K=2048 + softmax/top2/entropy.
// Epilogue reads logits from smem (no 64-reg array) -> higher occupancy.
// ---------------------------------------------------------------------------
__global__ __launch_bounds__(256, 2) void router_kernel(
    const float* __restrict__ W2, const float* __restrict__ b2,
    float* __restrict__ out)
{
    __shared__ float Hs[2][16][64];
    __shared__ float Ws[2][16][64];
    __shared__ float logits[64][65];
    __shared__ float entbuf[64];

    const int bm = blockIdx.x * 64;
    const int tid = threadIdx.x;

    const int lr = tid >> 2;
    const int lk = (tid & 3) << 2;

    const float* hg = g_h + (size_t)(bm + lr) * H_ + lk;
    const float* wg = W2  + (size_t)lr * H_ + lk;

    const int tx = tid & 15;
    const int ty = tid >> 4;

    float acc[4][4];
#pragma unroll
    for (int i = 0; i < 4; i++)
#pragma unroll
        for (int j = 0; j < 4; j++) acc[i][j] = 0.0f;

    float4 h4 = *(const float4*)hg;
    float4 w4 = *(const float4*)wg;
    int s = 0;
    Hs[0][lk + 0][lr] = h4.x; Hs[0][lk + 1][lr] = h4.y;
    Hs[0][lk + 2][lr] = h4.z; Hs[0][lk + 3][lr] = h4.w;
    Ws[0][lk + 0][lr] = w4.x; Ws[0][lk + 1][lr] = w4.y;
    Ws[0][lk + 2][lr] = w4.z; Ws[0][lk + 3][lr] = w4.w;
    __syncthreads();

    const int NIT = H_ / 16;
    for (int it = 0; it < NIT; ++it) {
        if (it + 1 < NIT) {
            h4 = *(const float4*)(hg + (it + 1) * 16);
            w4 = *(const float4*)(wg + (it + 1) * 16);
        }
#pragma unroll
        for (int kk = 0; kk < 16; kk++) {
            float4 hv = *(const float4*)&Hs[s][kk][ty * 4];
            float4 wv = *(const float4*)&Ws[s][kk][tx * 4];
            float a[4] = {hv.x, hv.y, hv.z, hv.w};
            float w[4] = {wv.x, wv.y, wv.z, wv.w};
#pragma unroll
            for (int i = 0; i < 4; i++)
#pragma unroll
                for (int j = 0; j < 4; j++)
                    acc[i][j] = fmaf(a[i], w[j], acc[i][j]);
        }
        if (it + 1 < NIT) {
            s ^= 1;
            Hs[s][lk + 0][lr] = h4.x; Hs[s][lk + 1][lr] = h4.y;
            Hs[s][lk + 2][lr] = h4.z; Hs[s][lk + 3][lr] = h4.w;
            Ws[s][lk + 0][lr] = w4.x; Ws[s][lk + 1][lr] = w4.y;
            Ws[s][lk + 2][lr] = w4.z; Ws[s][lk + 3][lr] = w4.w;
            __syncthreads();
        }
    }
    __syncthreads();

#pragma unroll
    for (int i = 0; i < 4; i++)
#pragma unroll
        for (int j = 0; j < 4; j++) {
            const int e = tx * 4 + j;
            logits[ty * 4 + i][e] = acc[i][j] + __ldg(&b2[e]);
        }
    __syncthreads();

    // Per-row epilogue on threads 0..63, logits streamed from smem.
    if (tid < 64) {
        const int row = tid;
        float lmax = -INFINITY;
#pragma unroll
        for (int e = 0; e < E_; e++) lmax = fmaxf(lmax, logits[row][e]);

        int i1 = 0; float v1 = logits[row][0];
#pragma unroll
        for (int e = 1; e < E_; e++) {
            const float le = logits[row][e];
            if (le > v1) { v1 = le; i1 = e; }
        }
        int i2 = -1; float v2 = -INFINITY;
#pragma unroll
        for (int e = 0; e < E_; e++) {
            const float le = logits[row][e];
            if (e != i1 && le > v2) { v2 = le; i2 = e; }
        }

        const float e1 = expf((v1 - lmax) * TEMP_INV);
        const float e2 = expf((v2 - lmax) * TEMP_INV);
        const float inv = 1.0f / (e1 + e2);

        float S = 0.0f;
#pragma unroll
        for (int e = 0; e < E_; e++) S += expf(logits[row][e] - lmax);
        const float invS = 1.0f / S;
        float ent = 0.0f;
#pragma unroll
        for (int e = 0; e < E_; e++) {
            const float p = expf(logits[row][e] - lmax) * invS;
            ent -= p * logf(p + 1e-10f);
        }

        const size_t grow = (size_t)bm + row;
        out[grow * 2 + 0] = e1 * inv;
        out[grow * 2 + 1] = e2 * inv;
        out[(size_t)B_ * K_ + grow * 2 + 0] = (float)i1;
        out[(size_t)B_ * K_ + grow * 2 + 1] = (float)i2;
        entbuf[tid] = ent;
    }
    __syncthreads();
    if (tid == 0) {
        float s2 = 0.0f;
#pragma unroll
        for (int r = 0; r < 64; r++) s2 += entbuf[r];
        g_ent[blockIdx.x] = s2;
    }
}

__global__ void finalize_kernel(float* __restrict__ out)
{
    if (threadIdx.x == 0) {
        float s = 0.0f;
        for (int i = 0; i < B_ / 64; i++) s += g_ent[i];
        out[(size_t)2 * B_ * K_] = s / (float)B_ / logf((float)E_);
    }
}

// ---------------------------------------------------------------------------
extern "C" void kernel_launch(void* const* d_in, const int* in_sizes, int n_in,
                              void* d_out, int out_size)
{
    const float* x  = (const float*)d_in[0];
    const float* W1 = (const float*)d_in[1];
    const float* b1 = (const float*)d_in[2];
    const float* W2 = (const float*)d_in[3];
    const float* b2 = (const float*)d_in[4];
    float* out = (float*)d_out;

    cudaFuncSetAttribute(gemm1_mma_kernel,
                         cudaFuncAttributeMaxDynamicSharedMemorySize, GEMM_SMEM);

    split_both_kernel<<<SPLIT_NB, 256>>>(x, W1);

    dim3 g1(B_ / TM, H_ / TN);   // (128, 16)
    gemm1_mma_kernel<<<g1, 256, GEMM_SMEM>>>(b1);

    router_kernel<<<B_ / 64, 256>>>(W2, b2, out);
    finalize_kernel<<<1, 32>>>(out);
}